// round 14
// baseline (speedup 1.0000x reference)
#include <cuda_runtime.h>

// LSTM2: 2-layer LSTM, B=1024, T=1024, H=64, input dim 1, output 1/step.
// Persistent-RNN: 128 CTAs x 256 threads, 8 batch rows per CTA (R8 mapping).
// Thread = (unit n, k-quarter kq): all 4 gates x 8 rows x 16 k per matrix,
// f32x2 FMAs, 2-level kq butterfly -> lane kq finalizes rows {kq, kq+4}.
// ROUND-14 CHANGES:
//  (a) chunked h layout: 16-float k-chunk c at offset c*24, row pitch 88.
//      Chunk bases hit banks {0,24,16,8} -> the 4 kq addresses of every
//      h LDS.128 use disjoint bank groups: 1 wavefront (was 2). Stores too.
//  (b) W1 (layer-1 weights) loaded ONCE into 32 u64 registers before the
//      T-loop -> removes 512 wf/SM/step and all L1 weight-load latency.

namespace {

constexpr int T_LEN = 1024;
constexpr int RPC   = 8;             // batch rows per CTA
constexpr int NTH   = 256;           // threads per CTA
constexpr int GRID  = 1024 / RPC;    // 128

constexpr int WP    = 68;            // weight row pitch (floats)
constexpr int HP    = 88;            // h row pitch (floats), chunked layout
constexpr int HB    = RPC * HP;      // 704 floats per h buffer

constexpr int SMEM_FLOATS = 3 * 256 * WP + 64 + 4 * HB + 16;
constexpr int SMEM_BYTES  = SMEM_FLOATS * 4;   // 220480 B (< 232448)

typedef unsigned long long u64;

__device__ __forceinline__ u64 fma2(u64 a, u64 b, u64 c) {
    u64 d;
    asm("fma.rn.f32x2 %0, %1, %2, %3;" : "=l"(d) : "l"(a), "l"(b), "l"(c));
    return d;
}
__device__ __forceinline__ float red2(u64 a) {
    return __uint_as_float((unsigned)a) + __uint_as_float((unsigned)(a >> 32));
}
__device__ __forceinline__ float tanh_f(float v) {
    float r;
    asm("tanh.approx.f32 %0, %1;" : "=f"(r) : "f"(v));
    return r;
}
__device__ __forceinline__ float sigm(float v) {
    return fmaf(tanh_f(0.5f * v), 0.5f, 0.5f);
}
__device__ __forceinline__ ulonglong2 ld2(const float* p) {
    return *(const ulonglong2*)p;
}
// chunked h column: k-chunk (k>>4) based at (k>>4)*24, contiguous within
__device__ __forceinline__ int hcol(int k) { return (k >> 4) * 24 + (k & 15); }

} // namespace

__global__ void __launch_bounds__(NTH, 1)
lstm2_kernel(const float* __restrict__ x,
             const float* __restrict__ w_ih1, const float* __restrict__ w_hh1,
             const float* __restrict__ b_ih1, const float* __restrict__ b_hh1,
             const float* __restrict__ w_ih2, const float* __restrict__ w_hh2,
             const float* __restrict__ b_ih2, const float* __restrict__ b_hh2,
             const float* __restrict__ w_lin, const float* __restrict__ b_lin,
             float* __restrict__ out)
{
    extern __shared__ float sm[];
    float* sWh1 = sm;                    // [256][68] (read once into regs)
    float* sWi2 = sWh1 + 256 * WP;       // [256][68]
    float* sWh2 = sWi2 + 256 * WP;       // [256][68]
    float* sWl  = sWh2 + 256 * WP;       // [64]
    float* sH1  = sWl + 64;              // [2][8][88] chunked
    float* sH2  = sH1 + 2 * HB;          // [2][8][88]
    float* sX   = sH2 + 2 * HB;          // [2][8]

    const int tid = threadIdx.x;
    const int rowbase = blockIdx.x * RPC;

    // ---- load weights into padded SMEM ----
    for (int i = tid; i < 256 * 64; i += NTH) {
        int j = i >> 6, k = i & 63;
        int off = j * WP + k;
        sWh1[off] = w_hh1[i];
        sWi2[off] = w_ih2[i];
        sWh2[off] = w_hh2[i];
    }
    if (tid < 64) sWl[tid] = w_lin[tid];
    for (int i = tid; i < 4 * HB; i += NTH) sH1[i] = 0.f;   // zeros h1 AND h2
    if (tid < RPC) sX[tid] = x[(rowbase + tid) * T_LEN];
    __syncthreads();

    // thread mapping: lane = kq*8 + nl; n = wid*8 + nl
    const int lid = tid & 31;
    const int wid = tid >> 5;
    const int kq  = lid >> 3;            // k-quarter 0..3
    const int n   = (wid << 3) | (lid & 7);
    const int kq16 = kq * 16;
    const int kq24 = kq * 24;            // chunk base in chunked h rows
    const int rA = kq, rB = kq + 4;      // rows this lane finalizes
    const int hi2 = kq & 2, hi1 = kq & 1;
    const int nst = hcol(n);             // store column of unit n

    // per-thread constants from GMEM (once)
    const float b1i = b_ih1[n]       + b_hh1[n];
    const float b1f = b_ih1[n + 64]  + b_hh1[n + 64];
    const float b1g = b_ih1[n + 128] + b_hh1[n + 128];
    const float b1o = b_ih1[n + 192] + b_hh1[n + 192];
    const float b2i = b_ih2[n]       + b_hh2[n];
    const float b2f = b_ih2[n + 64]  + b_hh2[n + 64];
    const float b2g = b_ih2[n + 128] + b_hh2[n + 128];
    const float b2o = b_ih2[n + 192] + b_hh2[n + 192];
    const float wxi = w_ih1[n],       wxf = w_ih1[n + 64];
    const float wxg = w_ih1[n + 128], wxo = w_ih1[n + 192];
    const float blin = b_lin[0];

    // layer-2 weight quarter base pointers (smem)
    const float* Ub = sWi2 + n * WP + kq16;
    const float* Vb = sWh2 + n * WP + kq16;

    // ---- W1 into registers, once (loop-invariant) ----
    ulonglong2 w1r[4][4];
    {
        const float* W1b = sWh1 + n * WP + kq16;
        #pragma unroll
        for (int g = 0; g < 4; ++g)
            #pragma unroll
            for (int i = 0; i < 4; ++i)
                w1r[g][i] = ld2(W1b + g * 64 * WP + i * 4);
    }

    // persistent cell state (this lane's two rows)
    float c1a = 0.f, c1b = 0.f, c2a = 0.f, c2b = 0.f;

    for (int t = 0; t < T_LEN; ++t) {
        const int p = t & 1, q = p ^ 1;

        // prefetch next x (hidden under compute)
        float xn = 0.f;
        if (tid < RPC) {
            int tn = (t + 1 < T_LEN) ? (t + 1) : t;
            xn = x[(rowbase + tid) * T_LEN + tn];
        }

        // ============ layer 1: W1(regs) x h1(p) ============
        {
            const float* hb = sH1 + p * HB + kq24;
            u64 acc[4][8] = {};
            #pragma unroll
            for (int i = 0; i < 4; ++i) {
                const int io = i * 4;
                #pragma unroll
                for (int r = 0; r < 8; ++r) {
                    ulonglong2 hv = ld2(hb + r * HP + io);
                    acc[0][r] = fma2(w1r[0][i].x, hv.x, acc[0][r]);
                    acc[0][r] = fma2(w1r[0][i].y, hv.y, acc[0][r]);
                    acc[1][r] = fma2(w1r[1][i].x, hv.x, acc[1][r]);
                    acc[1][r] = fma2(w1r[1][i].y, hv.y, acc[1][r]);
                    acc[2][r] = fma2(w1r[2][i].x, hv.x, acc[2][r]);
                    acc[2][r] = fma2(w1r[2][i].y, hv.y, acc[2][r]);
                    acc[3][r] = fma2(w1r[3][i].x, hv.x, acc[3][r]);
                    acc[3][r] = fma2(w1r[3][i].y, hv.y, acc[3][r]);
                }
            }
            // 2-level butterfly: lane kq ends with rows {kq, kq+4}
            float vA[4], vB[4];
            #pragma unroll
            for (int g = 0; g < 4; ++g) {
                float p0 = red2(acc[g][0]), p1 = red2(acc[g][1]);
                float p2 = red2(acc[g][2]), p3 = red2(acc[g][3]);
                float p4 = red2(acc[g][4]), p5 = red2(acc[g][5]);
                float p6 = red2(acc[g][6]), p7 = red2(acc[g][7]);
                float va0 = (hi2 ? p2 : p0) + __shfl_xor_sync(~0u, hi2 ? p0 : p2, 16);
                float va1 = (hi2 ? p3 : p1) + __shfl_xor_sync(~0u, hi2 ? p1 : p3, 16);
                float va4 = (hi2 ? p6 : p4) + __shfl_xor_sync(~0u, hi2 ? p4 : p6, 16);
                float va5 = (hi2 ? p7 : p5) + __shfl_xor_sync(~0u, hi2 ? p5 : p7, 16);
                vA[g] = (hi1 ? va1 : va0) + __shfl_xor_sync(~0u, hi1 ? va0 : va1, 8);
                vB[g] = (hi1 ? va5 : va4) + __shfl_xor_sync(~0u, hi1 ? va4 : va5, 8);
            }

            const float xsA = sX[p * RPC + rA];
            const float xsB = sX[p * RPC + rB];
            float ii = sigm(fmaf(wxi, xsA, b1i) + vA[0]);
            float ff = sigm(fmaf(wxf, xsA, b1f) + vA[1]);
            float gc = tanh_f(fmaf(wxg, xsA, b1g) + vA[2]);
            float oo = sigm(fmaf(wxo, xsA, b1o) + vA[3]);
            c1a = ff * c1a + ii * gc;
            sH1[q * HB + rA * HP + nst] = oo * tanh_f(c1a);
            ii = sigm(fmaf(wxi, xsB, b1i) + vB[0]);
            ff = sigm(fmaf(wxf, xsB, b1f) + vB[1]);
            gc = tanh_f(fmaf(wxg, xsB, b1g) + vB[2]);
            oo = sigm(fmaf(wxo, xsB, b1o) + vB[3]);
            c1b = ff * c1b + ii * gc;
            sH1[q * HB + rB * HP + nst] = oo * tanh_f(c1b);
        }
        if (tid < RPC) sX[q * RPC + tid] = xn;
        __syncthreads();   // bar1: h1(q) + x(q) published

        // ============ layer 2: U x h1(q) + V x h2(p) ============
        {
            u64 acc[4][8] = {};
            {
                const float* hb = sH1 + q * HB + kq24;
                #pragma unroll
                for (int i = 0; i < 4; ++i) {
                    const int io = i * 4;
                    ulonglong2 wv0 = ld2(Ub + io);
                    ulonglong2 wv1 = ld2(Ub + 64 * WP + io);
                    ulonglong2 wv2 = ld2(Ub + 128 * WP + io);
                    ulonglong2 wv3 = ld2(Ub + 192 * WP + io);
                    #pragma unroll
                    for (int r = 0; r < 8; ++r) {
                        ulonglong2 hv = ld2(hb + r * HP + io);
                        acc[0][r] = fma2(wv0.x, hv.x, acc[0][r]);
                        acc[0][r] = fma2(wv0.y, hv.y, acc[0][r]);
                        acc[1][r] = fma2(wv1.x, hv.x, acc[1][r]);
                        acc[1][r] = fma2(wv1.y, hv.y, acc[1][r]);
                        acc[2][r] = fma2(wv2.x, hv.x, acc[2][r]);
                        acc[2][r] = fma2(wv2.y, hv.y, acc[2][r]);
                        acc[3][r] = fma2(wv3.x, hv.x, acc[3][r]);
                        acc[3][r] = fma2(wv3.y, hv.y, acc[3][r]);
                    }
                }
            }
            {
                const float* hb = sH2 + p * HB + kq24;
                #pragma unroll
                for (int i = 0; i < 4; ++i) {
                    const int io = i * 4;
                    ulonglong2 wv0 = ld2(Vb + io);
                    ulonglong2 wv1 = ld2(Vb + 64 * WP + io);
                    ulonglong2 wv2 = ld2(Vb + 128 * WP + io);
                    ulonglong2 wv3 = ld2(Vb + 192 * WP + io);
                    #pragma unroll
                    for (int r = 0; r < 8; ++r) {
                        ulonglong2 hv = ld2(hb + r * HP + io);
                        acc[0][r] = fma2(wv0.x, hv.x, acc[0][r]);
                        acc[0][r] = fma2(wv0.y, hv.y, acc[0][r]);
                        acc[1][r] = fma2(wv1.x, hv.x, acc[1][r]);
                        acc[1][r] = fma2(wv1.y, hv.y, acc[1][r]);
                        acc[2][r] = fma2(wv2.x, hv.x, acc[2][r]);
                        acc[2][r] = fma2(wv2.y, hv.y, acc[2][r]);
                        acc[3][r] = fma2(wv3.x, hv.x, acc[3][r]);
                        acc[3][r] = fma2(wv3.y, hv.y, acc[3][r]);
                    }
                }
            }
            float vA[4], vB[4];
            #pragma unroll
            for (int g = 0; g < 4; ++g) {
                float p0 = red2(acc[g][0]), p1 = red2(acc[g][1]);
                float p2 = red2(acc[g][2]), p3 = red2(acc[g][3]);
                float p4 = red2(acc[g][4]), p5 = red2(acc[g][5]);
                float p6 = red2(acc[g][6]), p7 = red2(acc[g][7]);
                float va0 = (hi2 ? p2 : p0) + __shfl_xor_sync(~0u, hi2 ? p0 : p2, 16);
                float va1 = (hi2 ? p3 : p1) + __shfl_xor_sync(~0u, hi2 ? p1 : p3, 16);
                float va4 = (hi2 ? p6 : p4) + __shfl_xor_sync(~0u, hi2 ? p4 : p6, 16);
                float va5 = (hi2 ? p7 : p5) + __shfl_xor_sync(~0u, hi2 ? p5 : p7, 16);
                vA[g] = (hi1 ? va1 : va0) + __shfl_xor_sync(~0u, hi1 ? va0 : va1, 8);
                vB[g] = (hi1 ? va5 : va4) + __shfl_xor_sync(~0u, hi1 ? va4 : va5, 8);
            }
            float ii = sigm(b2i + vA[0]);
            float ff = sigm(b2f + vA[1]);
            float gc = tanh_f(b2g + vA[2]);
            float oo = sigm(b2o + vA[3]);
            c2a = ff * c2a + ii * gc;
            sH2[q * HB + rA * HP + nst] = oo * tanh_f(c2a);
            ii = sigm(b2i + vB[0]);
            ff = sigm(b2f + vB[1]);
            gc = tanh_f(b2g + vB[2]);
            oo = sigm(b2o + vB[3]);
            c2b = ff * c2b + ii * gc;
            sH2[q * HB + rB * HP + nst] = oo * tanh_f(c2b);
        }
        __syncthreads();   // bar2: h2(q) published

        // ====== output: warp w reduces row w of h2(q) against w_lin ======
        {
            const float* hr = sH2 + q * HB + wid * HP;
            float v = hr[hcol(lid)] * sWl[lid] + hr[hcol(lid + 32)] * sWl[lid + 32];
            #pragma unroll
            for (int off = 16; off; off >>= 1)
                v += __shfl_xor_sync(0xffffffffu, v, off);
            if (lid == 0) out[(rowbase + wid) * T_LEN + t] = v + blin;
        }
    }
}

extern "C" void kernel_launch(void* const* d_in, const int* in_sizes, int n_in,
                              void* d_out, int out_size)
{
    const float* x     = (const float*)d_in[0];
    const float* w_ih1 = (const float*)d_in[1];
    const float* w_hh1 = (const float*)d_in[2];
    const float* b_ih1 = (const float*)d_in[3];
    const float* b_hh1 = (const float*)d_in[4];
    const float* w_ih2 = (const float*)d_in[5];
    const float* w_hh2 = (const float*)d_in[6];
    const float* b_ih2 = (const float*)d_in[7];
    const float* b_hh2 = (const float*)d_in[8];
    const float* w_lin = (const float*)d_in[9];
    const float* b_lin = (const float*)d_in[10];

    cudaFuncSetAttribute(lstm2_kernel,
                         cudaFuncAttributeMaxDynamicSharedMemorySize, SMEM_BYTES);

    lstm2_kernel<<<GRID, NTH, SMEM_BYTES>>>(
        x, w_ih1, w_hh1, b_ih1, b_hh1,
        w_ih2, w_hh2, b_ih2, b_hh2,
        w_lin, b_lin, (float*)d_out);
}

// round 15
// speedup vs baseline: 1.8799x; 1.8799x over previous
#include <cuda_runtime.h>

// LSTM2: 2-layer LSTM, B=1024, T=1024, H=64, input dim 1, output 1/step.
// Persistent-RNN: 128 CTAs x 256 threads, 8 batch rows per CTA (R8 mapping).
// Thread = (unit n, k-quarter kq): all 4 gates x 8 rows x 16 k per matrix,
// f32x2 FMAs, 2-level kq butterfly -> lane kq finalizes rows {kq, kq+4}.
// R13 software-pipelined phases (V*h2(p) hoisted before bar1, partials
// carried in registers) + R15 CHANGE: chunked h layout ONLY (no reg-cached
// weights - R14 showed those halve FFMA2 throughput via RF banking):
//   h row pitch 88, 16-float k-chunk c at offset c*24 -> the 4 kq quad
//   addresses of every h LDS.128 hit disjoint bank groups {4i,4i+8,4i+16,
//   4i+24}: 1 wavefront (was 2). Stores (banks 24kq+n) also conflict-free.

namespace {

constexpr int T_LEN = 1024;
constexpr int RPC   = 8;             // batch rows per CTA
constexpr int NTH   = 256;           // threads per CTA
constexpr int GRID  = 1024 / RPC;    // 128

constexpr int WP    = 68;            // weight row pitch (floats)
constexpr int HP    = 88;            // h row pitch (floats), chunked layout
constexpr int HB    = RPC * HP;      // 704 floats per h buffer

constexpr int SMEM_FLOATS = 3 * 256 * WP + 64 + 4 * HB + 16;
constexpr int SMEM_BYTES  = SMEM_FLOATS * 4;   // 220480 B (< 232448)

typedef unsigned long long u64;

__device__ __forceinline__ u64 fma2(u64 a, u64 b, u64 c) {
    u64 d;
    asm("fma.rn.f32x2 %0, %1, %2, %3;" : "=l"(d) : "l"(a), "l"(b), "l"(c));
    return d;
}
__device__ __forceinline__ float red2(u64 a) {
    return __uint_as_float((unsigned)a) + __uint_as_float((unsigned)(a >> 32));
}
__device__ __forceinline__ float tanh_f(float v) {
    float r;
    asm("tanh.approx.f32 %0, %1;" : "=f"(r) : "f"(v));
    return r;
}
__device__ __forceinline__ float sigm(float v) {
    return fmaf(tanh_f(0.5f * v), 0.5f, 0.5f);
}
__device__ __forceinline__ ulonglong2 ld2(const float* p) {
    return *(const ulonglong2*)p;
}
// chunked h column: k-chunk (k>>4) based at (k>>4)*24, contiguous within
__device__ __forceinline__ int hcol(int k) { return (k >> 4) * 24 + (k & 15); }

} // namespace

__global__ void __launch_bounds__(NTH, 1)
lstm2_kernel(const float* __restrict__ x,
             const float* __restrict__ w_ih1, const float* __restrict__ w_hh1,
             const float* __restrict__ b_ih1, const float* __restrict__ b_hh1,
             const float* __restrict__ w_ih2, const float* __restrict__ w_hh2,
             const float* __restrict__ b_ih2, const float* __restrict__ b_hh2,
             const float* __restrict__ w_lin, const float* __restrict__ b_lin,
             float* __restrict__ out)
{
    extern __shared__ float sm[];
    float* sWh1 = sm;                    // [256][68]
    float* sWi2 = sWh1 + 256 * WP;       // [256][68]
    float* sWh2 = sWi2 + 256 * WP;       // [256][68]
    float* sWl  = sWh2 + 256 * WP;       // [64]
    float* sH1  = sWl + 64;              // [2][8][88] chunked
    float* sH2  = sH1 + 2 * HB;          // [2][8][88]
    float* sX   = sH2 + 2 * HB;          // [2][8]

    const int tid = threadIdx.x;
    const int rowbase = blockIdx.x * RPC;

    // ---- load weights into padded SMEM ----
    for (int i = tid; i < 256 * 64; i += NTH) {
        int j = i >> 6, k = i & 63;
        int off = j * WP + k;
        sWh1[off] = w_hh1[i];
        sWi2[off] = w_ih2[i];
        sWh2[off] = w_hh2[i];
    }
    if (tid < 64) sWl[tid] = w_lin[tid];
    for (int i = tid; i < 4 * HB; i += NTH) sH1[i] = 0.f;   // zeros h1 AND h2
    if (tid < RPC) sX[tid] = x[(rowbase + tid) * T_LEN];
    __syncthreads();

    // thread mapping: lane = kq*8 + nl; n = wid*8 + nl
    const int lid = tid & 31;
    const int wid = tid >> 5;
    const int kq  = lid >> 3;            // k-quarter 0..3
    const int n   = (wid << 3) | (lid & 7);
    const int kq16 = kq * 16;            // weight chunk base (pitch 68 rows)
    const int kq24 = kq * 24;            // h chunk base (chunked layout)
    const int rA = kq, rB = kq + 4;      // rows this lane finalizes
    const int hi2 = kq & 2, hi1 = kq & 1;
    const int nst = hcol(n);             // store column of unit n

    // per-thread constants from GMEM (once)
    const float b1i = b_ih1[n]       + b_hh1[n];
    const float b1f = b_ih1[n + 64]  + b_hh1[n + 64];
    const float b1g = b_ih1[n + 128] + b_hh1[n + 128];
    const float b1o = b_ih1[n + 192] + b_hh1[n + 192];
    const float b2i = b_ih2[n]       + b_hh2[n];
    const float b2f = b_ih2[n + 64]  + b_hh2[n + 64];
    const float b2g = b_ih2[n + 128] + b_hh2[n + 128];
    const float b2o = b_ih2[n + 192] + b_hh2[n + 192];
    const float wxi = w_ih1[n],       wxf = w_ih1[n + 64];
    const float wxg = w_ih1[n + 128], wxo = w_ih1[n + 192];
    const float blin = b_lin[0];

    // weight quarter base pointers
    const float* W1b = sWh1 + n * WP + kq16;    // layer1 w_hh (gate g at +g*64*WP)
    const float* Ub  = sWi2 + n * WP + kq16;    // layer2 w_ih
    const float* Vb  = sWh2 + n * WP + kq16;    // layer2 w_hh

    // persistent cell state (this lane's two rows)
    float c1a = 0.f, c1b = 0.f, c2a = 0.f, c2b = 0.f;

    for (int t = 0; t < T_LEN; ++t) {
        const int p = t & 1, q = p ^ 1;

        // prefetch next x (hidden under compute)
        float xn = 0.f;
        if (tid < RPC) {
            int tn = (t + 1 < T_LEN) ? (t + 1) : t;
            xn = x[(rowbase + tid) * T_LEN + tn];
        }

        // ================= PHASE 1 =================
        float pr2[4][8];           // V*h2(p) partials, carried across bar1
        {
            // ---- L1 dots: W1 x h1(p) ----
            u64 acc[4][8] = {};
            {
                const float* hb = sH1 + p * HB + kq24;
                #pragma unroll
                for (int i = 0; i < 4; ++i) {
                    const int io = i * 4;
                    ulonglong2 wv0 = ld2(W1b + io);
                    ulonglong2 wv1 = ld2(W1b + 64 * WP + io);
                    ulonglong2 wv2 = ld2(W1b + 128 * WP + io);
                    ulonglong2 wv3 = ld2(W1b + 192 * WP + io);
                    #pragma unroll
                    for (int r = 0; r < 8; ++r) {
                        ulonglong2 hv = ld2(hb + r * HP + io);
                        acc[0][r] = fma2(wv0.x, hv.x, acc[0][r]);
                        acc[0][r] = fma2(wv0.y, hv.y, acc[0][r]);
                        acc[1][r] = fma2(wv1.x, hv.x, acc[1][r]);
                        acc[1][r] = fma2(wv1.y, hv.y, acc[1][r]);
                        acc[2][r] = fma2(wv2.x, hv.x, acc[2][r]);
                        acc[2][r] = fma2(wv2.y, hv.y, acc[2][r]);
                        acc[3][r] = fma2(wv3.x, hv.x, acc[3][r]);
                        acc[3][r] = fma2(wv3.y, hv.y, acc[3][r]);
                    }
                }
            }
            // ---- bfly for L1 (shfl chains overlap with V dots below) ----
            float vA1[4], vB1[4];
            #pragma unroll
            for (int g = 0; g < 4; ++g) {
                float p0 = red2(acc[g][0]), p1 = red2(acc[g][1]);
                float p2 = red2(acc[g][2]), p3 = red2(acc[g][3]);
                float p4 = red2(acc[g][4]), p5 = red2(acc[g][5]);
                float p6 = red2(acc[g][6]), p7 = red2(acc[g][7]);
                float va0 = (hi2 ? p2 : p0) + __shfl_xor_sync(~0u, hi2 ? p0 : p2, 16);
                float va1 = (hi2 ? p3 : p1) + __shfl_xor_sync(~0u, hi2 ? p1 : p3, 16);
                float va4 = (hi2 ? p6 : p4) + __shfl_xor_sync(~0u, hi2 ? p4 : p6, 16);
                float va5 = (hi2 ? p7 : p5) + __shfl_xor_sync(~0u, hi2 ? p5 : p7, 16);
                vA1[g] = (hi1 ? va1 : va0) + __shfl_xor_sync(~0u, hi1 ? va0 : va1, 8);
                vB1[g] = (hi1 ? va5 : va4) + __shfl_xor_sync(~0u, hi1 ? va4 : va5, 8);
            }
            // ---- V dots: V x h2(p)  (no barrier dependency) ----
            u64 accv[4][8] = {};
            {
                const float* hb = sH2 + p * HB + kq24;
                #pragma unroll
                for (int i = 0; i < 4; ++i) {
                    const int io = i * 4;
                    ulonglong2 wv0 = ld2(Vb + io);
                    ulonglong2 wv1 = ld2(Vb + 64 * WP + io);
                    ulonglong2 wv2 = ld2(Vb + 128 * WP + io);
                    ulonglong2 wv3 = ld2(Vb + 192 * WP + io);
                    #pragma unroll
                    for (int r = 0; r < 8; ++r) {
                        ulonglong2 hv = ld2(hb + r * HP + io);
                        accv[0][r] = fma2(wv0.x, hv.x, accv[0][r]);
                        accv[0][r] = fma2(wv0.y, hv.y, accv[0][r]);
                        accv[1][r] = fma2(wv1.x, hv.x, accv[1][r]);
                        accv[1][r] = fma2(wv1.y, hv.y, accv[1][r]);
                        accv[2][r] = fma2(wv2.x, hv.x, accv[2][r]);
                        accv[2][r] = fma2(wv2.y, hv.y, accv[2][r]);
                        accv[3][r] = fma2(wv3.x, hv.x, accv[3][r]);
                        accv[3][r] = fma2(wv3.y, hv.y, accv[3][r]);
                    }
                }
            }
            #pragma unroll
            for (int g = 0; g < 4; ++g)
                #pragma unroll
                for (int r = 0; r < 8; ++r)
                    pr2[g][r] = red2(accv[g][r]);

            // ---- L1 epilogue (rows rA, rB) ----
            const float xsA = sX[p * RPC + rA];
            const float xsB = sX[p * RPC + rB];
            float ii = sigm(fmaf(wxi, xsA, b1i) + vA1[0]);
            float ff = sigm(fmaf(wxf, xsA, b1f) + vA1[1]);
            float gc = tanh_f(fmaf(wxg, xsA, b1g) + vA1[2]);
            float oo = sigm(fmaf(wxo, xsA, b1o) + vA1[3]);
            c1a = ff * c1a + ii * gc;
            sH1[q * HB + rA * HP + nst] = oo * tanh_f(c1a);
            ii = sigm(fmaf(wxi, xsB, b1i) + vB1[0]);
            ff = sigm(fmaf(wxf, xsB, b1f) + vB1[1]);
            gc = tanh_f(fmaf(wxg, xsB, b1g) + vB1[2]);
            oo = sigm(fmaf(wxo, xsB, b1o) + vB1[3]);
            c1b = ff * c1b + ii * gc;
            sH1[q * HB + rB * HP + nst] = oo * tanh_f(c1b);
        }
        if (tid < RPC) sX[q * RPC + tid] = xn;
        __syncthreads();   // bar1: h1(q) + x(q) published

        // ================= PHASE 2: U x h1(q) + V-partials =================
        {
            u64 acc[4][8] = {};
            {
                const float* hb = sH1 + q * HB + kq24;
                #pragma unroll
                for (int i = 0; i < 4; ++i) {
                    const int io = i * 4;
                    ulonglong2 wv0 = ld2(Ub + io);
                    ulonglong2 wv1 = ld2(Ub + 64 * WP + io);
                    ulonglong2 wv2 = ld2(Ub + 128 * WP + io);
                    ulonglong2 wv3 = ld2(Ub + 192 * WP + io);
                    #pragma unroll
                    for (int r = 0; r < 8; ++r) {
                        ulonglong2 hv = ld2(hb + r * HP + io);
                        acc[0][r] = fma2(wv0.x, hv.x, acc[0][r]);
                        acc[0][r] = fma2(wv0.y, hv.y, acc[0][r]);
                        acc[1][r] = fma2(wv1.x, hv.x, acc[1][r]);
                        acc[1][r] = fma2(wv1.y, hv.y, acc[1][r]);
                        acc[2][r] = fma2(wv2.x, hv.x, acc[2][r]);
                        acc[2][r] = fma2(wv2.y, hv.y, acc[2][r]);
                        acc[3][r] = fma2(wv3.x, hv.x, acc[3][r]);
                        acc[3][r] = fma2(wv3.y, hv.y, acc[3][r]);
                    }
                }
            }
            float vA[4], vB[4];
            #pragma unroll
            for (int g = 0; g < 4; ++g) {
                float p0 = red2(acc[g][0]) + pr2[g][0];
                float p1 = red2(acc[g][1]) + pr2[g][1];
                float p2 = red2(acc[g][2]) + pr2[g][2];
                float p3 = red2(acc[g][3]) + pr2[g][3];
                float p4 = red2(acc[g][4]) + pr2[g][4];
                float p5 = red2(acc[g][5]) + pr2[g][5];
                float p6 = red2(acc[g][6]) + pr2[g][6];
                float p7 = red2(acc[g][7]) + pr2[g][7];
                float va0 = (hi2 ? p2 : p0) + __shfl_xor_sync(~0u, hi2 ? p0 : p2, 16);
                float va1 = (hi2 ? p3 : p1) + __shfl_xor_sync(~0u, hi2 ? p1 : p3, 16);
                float va4 = (hi2 ? p6 : p4) + __shfl_xor_sync(~0u, hi2 ? p4 : p6, 16);
                float va5 = (hi2 ? p7 : p5) + __shfl_xor_sync(~0u, hi2 ? p5 : p7, 16);
                vA[g] = (hi1 ? va1 : va0) + __shfl_xor_sync(~0u, hi1 ? va0 : va1, 8);
                vB[g] = (hi1 ? va5 : va4) + __shfl_xor_sync(~0u, hi1 ? va4 : va5, 8);
            }
            float ii = sigm(b2i + vA[0]);
            float ff = sigm(b2f + vA[1]);
            float gc = tanh_f(b2g + vA[2]);
            float oo = sigm(b2o + vA[3]);
            c2a = ff * c2a + ii * gc;
            sH2[q * HB + rA * HP + nst] = oo * tanh_f(c2a);
            ii = sigm(b2i + vB[0]);
            ff = sigm(b2f + vB[1]);
            gc = tanh_f(b2g + vB[2]);
            oo = sigm(b2o + vB[3]);
            c2b = ff * c2b + ii * gc;
            sH2[q * HB + rB * HP + nst] = oo * tanh_f(c2b);
        }
        __syncthreads();   // bar2: h2(q) published

        // ====== output: warp w reduces row w of h2(q) against w_lin ======
        {
            const float* hr = sH2 + q * HB + wid * HP;
            float v = hr[hcol(lid)] * sWl[lid] + hr[hcol(lid + 32)] * sWl[lid + 32];
            #pragma unroll
            for (int off = 16; off; off >>= 1)
                v += __shfl_xor_sync(0xffffffffu, v, off);
            if (lid == 0) out[(rowbase + wid) * T_LEN + t] = v + blin;
        }
    }
}

extern "C" void kernel_launch(void* const* d_in, const int* in_sizes, int n_in,
                              void* d_out, int out_size)
{
    const float* x     = (const float*)d_in[0];
    const float* w_ih1 = (const float*)d_in[1];
    const float* w_hh1 = (const float*)d_in[2];
    const float* b_ih1 = (const float*)d_in[3];
    const float* b_hh1 = (const float*)d_in[4];
    const float* w_ih2 = (const float*)d_in[5];
    const float* w_hh2 = (const float*)d_in[6];
    const float* b_ih2 = (const float*)d_in[7];
    const float* b_hh2 = (const float*)d_in[8];
    const float* w_lin = (const float*)d_in[9];
    const float* b_lin = (const float*)d_in[10];

    cudaFuncSetAttribute(lstm2_kernel,
                         cudaFuncAttributeMaxDynamicSharedMemorySize, SMEM_BYTES);

    lstm2_kernel<<<GRID, NTH, SMEM_BYTES>>>(
        x, w_ih1, w_hh1, b_ih1, b_hh1,
        w_ih2, w_hh2, b_ih2, b_hh2,
        w_lin, b_lin, (float*)d_out);
}